// round 8
// baseline (speedup 1.0000x reference)
#include <cuda_runtime.h>
#include <math.h>

#define BNUM 16
#define LNUM 20
#define CNUM 256
#define DT   768

typedef unsigned long long ull;

// ---------------- scratch ----------------
__device__ float g_K[BNUM*LNUM*CNUM];
__device__ float g_V[BNUM*LNUM*CNUM];
__device__ float g_M[BNUM*LNUM*CNUM];
__device__ float g_G[BNUM*LNUM*LNUM];
__device__ float g_scale[BNUM*CNUM];
__device__ float g_beta[BNUM*CNUM];
__device__ float g_vec2[BNUM*2];
__device__ int   g_maxbuf[64];
__device__ __align__(16) float g_gate_raw[348160];
__device__ __align__(16) float g_gi[348160];

// ---------------- constants ----------------
__constant__ int   c_HW[4]      = {16384, 4096, 1024, 256};
__constant__ int   c_W[4]       = {128, 64, 32, 16};
__constant__ int   c_lw[4]      = {7, 6, 5, 4};
__constant__ int   c_pixBase[4] = {0, 262144, 327680, 344064};
__constant__ int   c_gateOut[4] = {89128960, 89391104, 89456640, 89473024};
__constant__ float c_step[4]    = {2.f/127.f, 2.f/63.f, 2.f/31.f, 2.f/15.f};

// ---------------- packed f32x2 helpers ----------------
__device__ __forceinline__ ull pk2(float lo, float hi) {
    ull r;
    asm("mov.b64 %0,{%1,%2};" : "=l"(r) : "f"(lo), "f"(hi));
    return r;
}
__device__ __forceinline__ void fma2(ull& d, ull a, ull b) {
    asm("fma.rn.f32x2 %0,%1,%2,%0;" : "+l"(d) : "l"(a), "l"(b));
}
__device__ __forceinline__ float2 unpk2(ull v) {
    float2 f;
    asm("mov.b64 {%0,%1},%2;" : "=f"(f.x), "=f"(f.y) : "l"(v));
    return f;
}

// ================= prep: blocks 0..39 = KV tiles (8 rows); 40..55 = mod MLPs =================
#define KV_ROWS 8
__global__ __launch_bounds__(256) void prep_kernel(
    const float* __restrict__ wt, const float* __restrict__ Wk, const float* __restrict__ Wv,
    const float* __restrict__ sent,
    const float* __restrict__ gw1, const float* __restrict__ gb1,
    const float* __restrict__ gw2, const float* __restrict__ gb2,
    const float* __restrict__ bw1, const float* __restrict__ bb1,
    const float* __restrict__ bw2, const float* __restrict__ bb2,
    const float* __restrict__ dw1, const float* __restrict__ db1,
    const float* __restrict__ dw2, const float* __restrict__ db2)
{
    __shared__ __align__(16) float swt[KV_ROWS*DT];
    __shared__ __align__(16) float ss[DT];
    __shared__ float sh[CNUM];
    int t = threadIdx.x;
    int bid = blockIdx.x;

    if (bid < 40) {
        if (bid == 0 && t < 64) g_maxbuf[t] = 0;
        int r0 = bid * KV_ROWS;
        for (int i = t; i < KV_ROWS*DT; i += 256) swt[i] = wt[(size_t)r0*DT + i];
        __syncthreads();
        float aK[KV_ROWS], aV[KV_ROWS];
#pragma unroll
        for (int r = 0; r < KV_ROWS; ++r) { aK[r] = 0.f; aV[r] = 0.f; }
        int c = t;
        for (int d = 0; d < DT; d += 4) {
            float k0 = Wk[(d+0)*CNUM + c], k1 = Wk[(d+1)*CNUM + c];
            float k2 = Wk[(d+2)*CNUM + c], k3 = Wk[(d+3)*CNUM + c];
            float v0 = Wv[(d+0)*CNUM + c], v1 = Wv[(d+1)*CNUM + c];
            float v2 = Wv[(d+2)*CNUM + c], v3 = Wv[(d+3)*CNUM + c];
#pragma unroll
            for (int r = 0; r < KV_ROWS; ++r) {
                float4 w = *reinterpret_cast<const float4*>(&swt[r*DT + d]);
                aK[r] = fmaf(w.x, k0, aK[r]); aK[r] = fmaf(w.y, k1, aK[r]);
                aK[r] = fmaf(w.z, k2, aK[r]); aK[r] = fmaf(w.w, k3, aK[r]);
                aV[r] = fmaf(w.x, v0, aV[r]); aV[r] = fmaf(w.y, v1, aV[r]);
                aV[r] = fmaf(w.z, v2, aV[r]); aV[r] = fmaf(w.w, v3, aV[r]);
            }
        }
#pragma unroll
        for (int r = 0; r < KV_ROWS; ++r) {
            g_K[(r0 + r)*CNUM + c] = aK[r];
            g_V[(r0 + r)*CNUM + c] = aV[r];
        }
    } else {
        int b = bid - 40;
        for (int i = t; i < DT; i += 256) ss[i] = sent[b*DT + i];
        __syncthreads();
        {
            float a0=0,a1=0,a2=0,a3=0;
            for (int d = 0; d < DT; d += 4) {
                float4 s = *reinterpret_cast<const float4*>(&ss[d]);
                a0 = fmaf(s.x, gw1[(d+0)*CNUM + t], a0);
                a1 = fmaf(s.y, gw1[(d+1)*CNUM + t], a1);
                a2 = fmaf(s.z, gw1[(d+2)*CNUM + t], a2);
                a3 = fmaf(s.w, gw1[(d+3)*CNUM + t], a3);
            }
            sh[t] = fmaxf((a0+a1)+(a2+a3) + gb1[t], 0.f);
        }
        __syncthreads();
        {
            float a0=0,a1=0,a2=0,a3=0;
            for (int j = 0; j < CNUM; j += 4) {
                float4 s = *reinterpret_cast<const float4*>(&sh[j]);
                a0 = fmaf(s.x, gw2[(j+0)*CNUM + t], a0);
                a1 = fmaf(s.y, gw2[(j+1)*CNUM + t], a1);
                a2 = fmaf(s.z, gw2[(j+2)*CNUM + t], a2);
                a3 = fmaf(s.w, gw2[(j+3)*CNUM + t], a3);
            }
            g_scale[b*CNUM + t] = 1.f + (a0+a1)+(a2+a3) + gb2[t];
        }
        __syncthreads();
        {
            float a0=0,a1=0,a2=0,a3=0;
            for (int d = 0; d < DT; d += 4) {
                float4 s = *reinterpret_cast<const float4*>(&ss[d]);
                a0 = fmaf(s.x, bw1[(d+0)*CNUM + t], a0);
                a1 = fmaf(s.y, bw1[(d+1)*CNUM + t], a1);
                a2 = fmaf(s.z, bw1[(d+2)*CNUM + t], a2);
                a3 = fmaf(s.w, bw1[(d+3)*CNUM + t], a3);
            }
            sh[t] = fmaxf((a0+a1)+(a2+a3) + bb1[t], 0.f);
        }
        __syncthreads();
        {
            float a0=0,a1=0,a2=0,a3=0;
            for (int j = 0; j < CNUM; j += 4) {
                float4 s = *reinterpret_cast<const float4*>(&sh[j]);
                a0 = fmaf(s.x, bw2[(j+0)*CNUM + t], a0);
                a1 = fmaf(s.y, bw2[(j+1)*CNUM + t], a1);
                a2 = fmaf(s.z, bw2[(j+2)*CNUM + t], a2);
                a3 = fmaf(s.w, bw2[(j+3)*CNUM + t], a3);
            }
            g_beta[b*CNUM + t] = (a0+a1)+(a2+a3) + bb2[t];
        }
        __syncthreads();
        if (t < 64) {
            float a0=0,a1=0,a2=0,a3=0;
            for (int d = 0; d < DT; d += 4) {
                float4 s = *reinterpret_cast<const float4*>(&ss[d]);
                a0 = fmaf(s.x, dw1[(d+0)*64 + t], a0);
                a1 = fmaf(s.y, dw1[(d+1)*64 + t], a1);
                a2 = fmaf(s.z, dw1[(d+2)*64 + t], a2);
                a3 = fmaf(s.w, dw1[(d+3)*64 + t], a3);
            }
            sh[t] = fmaxf((a0+a1)+(a2+a3) + db1[t], 0.f);
        }
        __syncthreads();
        if (t == 0) {
            float v0 = db2[0], v1 = db2[1];
            for (int j = 0; j < 64; ++j) {
                v0 = fmaf(sh[j], dw2[j*2 + 0], v0);
                v1 = fmaf(sh[j], dw2[j*2 + 1], v1);
            }
            float nrm = fmaxf(sqrtf(v0*v0 + v1*v1), 1e-12f);
            g_vec2[b*2 + 0] = v0 / nrm;
            g_vec2[b*2 + 1] = v1 / nrm;
        }
    }
}

// ================= blocks 0..39: M = (K@Wq)/16; 40..55: G = V@V^T =================
__global__ __launch_bounds__(256) void mv_kernel(const float* __restrict__ Wq) {
    __shared__ __align__(16) float sK[KV_ROWS*CNUM];
    __shared__ __align__(16) float sV[LNUM*CNUM];
    int t = threadIdx.x;
    int bid = blockIdx.x;
    if (bid < 40) {
        int r0 = bid * KV_ROWS;
        for (int i = t; i < KV_ROWS*CNUM; i += 256) sK[i] = g_K[r0*CNUM + i];
        __syncthreads();
        float acc[KV_ROWS];
#pragma unroll
        for (int r = 0; r < KV_ROWS; ++r) acc[r] = 0.f;
        int c = t;
        for (int o = 0; o < CNUM; o += 4) {
            float q0 = Wq[(o+0)*CNUM + c], q1 = Wq[(o+1)*CNUM + c];
            float q2 = Wq[(o+2)*CNUM + c], q3 = Wq[(o+3)*CNUM + c];
#pragma unroll
            for (int r = 0; r < KV_ROWS; ++r) {
                float4 k = *reinterpret_cast<const float4*>(&sK[r*CNUM + o]);
                acc[r] = fmaf(k.x, q0, acc[r]); acc[r] = fmaf(k.y, q1, acc[r]);
                acc[r] = fmaf(k.z, q2, acc[r]); acc[r] = fmaf(k.w, q3, acc[r]);
            }
        }
#pragma unroll
        for (int r = 0; r < KV_ROWS; ++r)
            g_M[(r0 + r)*CNUM + c] = acc[r] * 0.0625f;
    } else {
        int b = bid - 40;
        for (int i = t; i < LNUM*CNUM; i += 256) sV[i] = g_V[b*LNUM*CNUM + i];
        __syncthreads();
        for (int e = t; e < LNUM*LNUM; e += 256) {
            int l  = e / LNUM;
            int l2 = e % LNUM;
            float a0=0,a1=0,a2=0,a3=0;
            for (int c = 0; c < CNUM; c += 4) {
                float4 x = *reinterpret_cast<const float4*>(&sV[l*CNUM + c]);
                float4 y = *reinterpret_cast<const float4*>(&sV[l2*CNUM + c]);
                a0 = fmaf(x.x, y.x, a0); a1 = fmaf(x.y, y.y, a1);
                a2 = fmaf(x.z, y.z, a2); a3 = fmaf(x.w, y.w, a3);
            }
            g_G[b*LNUM*LNUM + e] = (a0+a1)+(a2+a3);
        }
    }
}

// ---------------- block decode: 688 blocks (phaseA / phaseA2) ----------------
__device__ __forceinline__ void decode_block(int bid, int& level, int& b, int& tile) {
    if (bid < 512)      { level = 0; b = bid >> 5; tile = bid & 31; }
    else if (bid < 640) { int r = bid - 512; level = 1; b = r >> 3; tile = r & 7; }
    else if (bid < 672) { int r = bid - 640; level = 2; b = r >> 1; tile = r & 1; }
    else                { level = 3; b = bid - 672; tile = 0; }
}

// ---------------- phaseA core ----------------
template<int HW>
__device__ __forceinline__ void phaseA_core(const float* __restrict__ F, int b, int n0,
                                            const ull* __restrict__ sM2,
                                            const ull* __restrict__ sG2,
                                            const int* __restrict__ smask,
                                            int pbase, int maxSlot) {
    const float* p = F + (size_t)b * CNUM * HW + n0;

    ull acc[LNUM];
#pragma unroll
    for (int l = 0; l < LNUM; ++l) acc[l] = 0ull;

#pragma unroll 8
    for (int c = 0; c < CNUM; c += 2) {
        ull fa = __ldcs(reinterpret_cast<const ull*>(p));
        ull fb = __ldcs(reinterpret_cast<const ull*>(p + HW));
        p += 2 * HW;
#pragma unroll
        for (int l = 0; l < LNUM; ++l) {
            ulonglong2 m = *reinterpret_cast<const ulonglong2*>(&sM2[l*CNUM + c]);
            fma2(acc[l], fa, m.x);
            fma2(acc[l], fb, m.y);
        }
    }

    float2 mx = make_float2(-1e30f, -1e30f);
#pragma unroll
    for (int l = 0; l < LNUM; ++l) {
        if (smask[l]) {
            float2 u = unpk2(acc[l]);
            mx.x = fmaxf(mx.x, u.x);
            mx.y = fmaxf(mx.y, u.y);
        }
    }
    float2 sm = make_float2(0.f, 0.f);
#pragma unroll
    for (int l = 0; l < LNUM; ++l) {
        int mk = smask[l];
        float2 u = unpk2(acc[l]);
        float e0 = mk ? __expf(u.x - mx.x) : 0.f;
        float e1 = mk ? __expf(u.y - mx.y) : 0.f;
        sm.x += e0; sm.y += e1;
        acc[l] = pk2(e0, e1);
    }

    ull gs = 0ull;
#pragma unroll
    for (int l = 0; l < LNUM; ++l) {
        ull tt = 0ull;
#pragma unroll
        for (int l2 = 0; l2 < LNUM; l2 += 2) {
            ulonglong2 gg = *reinterpret_cast<const ulonglong2*>(&sG2[l*LNUM + l2]);
            fma2(tt, acc[l2],   gg.x);
            fma2(tt, acc[l2+1], gg.y);
        }
        fma2(gs, acc[l], tt);
    }
    float2 g0 = unpk2(gs);
    float2 gt;
    gt.x = sqrtf(fmaxf(g0.x, 0.f)) * __fdividef(1.f, sm.x);
    gt.y = sqrtf(fmaxf(g0.y, 0.f)) * __fdividef(1.f, sm.y);
    *reinterpret_cast<float2*>(&g_gate_raw[pbase + n0]) = gt;
    atomicMax(&g_maxbuf[maxSlot], __float_as_int(fmaxf(gt.x, gt.y)));
}

// ================= Phase A =================
__global__ __launch_bounds__(256, 4) void phaseA(const float* __restrict__ f0,
                                                 const float* __restrict__ f1,
                                                 const float* __restrict__ f2,
                                                 const float* __restrict__ f3,
                                                 const int* __restrict__ mask) {
    __shared__ __align__(16) ull sM2[LNUM*CNUM];
    __shared__ __align__(16) ull sG2[LNUM*LNUM];
    __shared__ int smask[LNUM];

    int level, b, tile;
    decode_block(blockIdx.x, level, b, tile);
    int t = threadIdx.x;
    int bbase = b * LNUM * CNUM;
    for (int i = t; i < LNUM*CNUM; i += 256) { float m = g_M[bbase + i]; sM2[i] = pk2(m, m); }
    for (int i = t; i < LNUM*LNUM; i += 256) { float g = g_G[b*LNUM*LNUM + i]; sG2[i] = pk2(g, g); }
    if (t < LNUM) smask[t] = mask[b*LNUM + t];
    __syncthreads();

    int n0 = tile * 512 + 2 * t;
    if (level == 0)
        phaseA_core<16384>(f0, b, n0, sM2, sG2, smask, b*16384,          b);
    else if (level == 1)
        phaseA_core< 4096>(f1, b, n0, sM2, sG2, smask, 262144 + b*4096, 16 + b);
    else if (level == 2)
        phaseA_core< 1024>(f2, b, n0, sM2, sG2, smask, 327680 + b*1024, 32 + b);
    else if (t < 128)
        phaseA_core<  256>(f3, b, 2*t, sM2, sG2, smask, 344064 + b*256, 48 + b);
}

// ================= Phase A2 =================
__global__ __launch_bounds__(256) void phaseA2(float* __restrict__ out) {
    int level, b, tile;
    decode_block(blockIdx.x, level, b, tile);
    int t = threadIdx.x;
    const int HW = c_HW[level];
    const int W  = c_W[level];
    const int lw = c_lw[level];
    float step = c_step[level];
    float v0 = g_vec2[2*b], v1 = g_vec2[2*b + 1];
    float mxv = __int_as_float(g_maxbuf[level*16 + b]) + 1e-6f;
    int pbase = c_pixBase[level] + b*HW;
    int obase = c_gateOut[level] + b*HW;
#pragma unroll
    for (int p = 0; p < 2; ++p) {
        int n = tile * 512 + t + p * 256;
        if (n >= HW) break;
        int w = n & (W - 1);
        int h = n >> lw;
        float x = fmaf((float)w, step, -1.f);
        float y = fmaf((float)h, step, -1.f);
        float pr = v0 * x + v1 * y;
        float di = __fdividef(1.f, 1.f + __expf(-pr));
        float gi = __fdividef(g_gate_raw[pbase + n], mxv) * di;
        g_gi[pbase + n] = gi;
        out[obase + n] = gi;
    }
}

// ================= Phase B (R6 flat): 4 consecutive float4/thread =================
template<int HW, int LG>
__device__ __forceinline__ void phaseB_core(const float* __restrict__ F,
                                            float* __restrict__ out,
                                            int g, int pixBase) {
    int n4   = g & (HW/4 - 1);
    int rest = g >> LG;
    int c = rest & 255;
    int b = rest >> 8;
    float sc = g_scale[b*CNUM + c];
    float be = g_beta[b*CNUM + c];
    const float4* fp = reinterpret_cast<const float4*>(F) + g;
    const float4* gp = reinterpret_cast<const float4*>(&g_gi[pixBase + b*HW]) + n4;
    float4*       op = reinterpret_cast<float4*>(out) + g;
#pragma unroll
    for (int j = 0; j < 4; ++j) {
        float4 f  = __ldcs(&fp[j]);
        float4 gi = gp[j];
        float4 o;
        o.x = fmaf(gi.x * f.x, sc, be);
        o.y = fmaf(gi.y * f.y, sc, be);
        o.z = fmaf(gi.z * f.z, sc, be);
        o.w = fmaf(gi.w * f.w, sc, be);
        __stcs(&op[j], o);
    }
}

__global__ __launch_bounds__(256) void phaseB(const float* __restrict__ f0,
                                              const float* __restrict__ f1,
                                              const float* __restrict__ f2,
                                              const float* __restrict__ f3,
                                              float* __restrict__ out) {
    int bid = blockIdx.x;
    int t = threadIdx.x;
    if (bid < 16384) {
        int g = bid * 1024 + t * 4;
        phaseB_core<16384, 12>(f0, out, g, 0);
    } else if (bid < 20480) {
        int g = (bid - 16384) * 1024 + t * 4;
        phaseB_core<4096, 10>(f1, out + 67108864, g, 262144);
    } else if (bid < 21504) {
        int g = (bid - 20480) * 1024 + t * 4;
        phaseB_core<1024, 8>(f2, out + 83886080, g, 327680);
    } else {
        int g = (bid - 21504) * 1024 + t * 4;
        phaseB_core<256, 6>(f3, out + 88080384, g, 344064);
    }
}

// ================= launch =================
extern "C" void kernel_launch(void* const* d_in, const int* in_sizes, int n_in,
                              void* d_out, int out_size) {
    const float* f0   = (const float*)d_in[0];
    const float* f1   = (const float*)d_in[1];
    const float* f2   = (const float*)d_in[2];
    const float* f3   = (const float*)d_in[3];
    const float* wt   = (const float*)d_in[4];
    const float* sent = (const float*)d_in[5];
    const int*   mask = (const int*)  d_in[6];
    const float* Wq   = (const float*)d_in[7];
    const float* Wk   = (const float*)d_in[8];
    const float* Wv   = (const float*)d_in[9];
    const float* gw1  = (const float*)d_in[10];
    const float* gb1  = (const float*)d_in[11];
    const float* gw2  = (const float*)d_in[12];
    const float* gb2  = (const float*)d_in[13];
    const float* bw1  = (const float*)d_in[14];
    const float* bb1  = (const float*)d_in[15];
    const float* bw2  = (const float*)d_in[16];
    const float* bb2  = (const float*)d_in[17];
    const float* dw1  = (const float*)d_in[18];
    const float* db1  = (const float*)d_in[19];
    const float* dw2  = (const float*)d_in[20];
    const float* db2  = (const float*)d_in[21];
    float* out = (float*)d_out;

    prep_kernel<<<56, 256>>>(wt, Wk, Wv, sent, gw1, gb1, gw2, gb2,
                             bw1, bb1, bw2, bb2, dw1, db1, dw2, db2);
    mv_kernel<<<56, 256>>>(Wq);
    phaseA<<<688, 256>>>(f0, f1, f2, f3, mask);
    phaseA2<<<688, 256>>>(out);
    phaseB<<<21760, 256>>>(f0, f1, f2, f3, out);
}

// round 10
// speedup vs baseline: 1.1051x; 1.1051x over previous
#include <cuda_runtime.h>
#include <math.h>

#define BNUM 16
#define LNUM 20
#define CNUM 256
#define DT   768

typedef unsigned long long ull;

// ---------------- scratch ----------------
__device__ float g_K[BNUM*LNUM*CNUM];
__device__ float g_V[BNUM*LNUM*CNUM];
__device__ float g_M[BNUM*LNUM*CNUM];
__device__ float g_G[BNUM*LNUM*LNUM];
__device__ float g_scale[BNUM*CNUM];
__device__ float g_beta[BNUM*CNUM];
__device__ float g_vec2[BNUM*2];
__device__ int   g_maxbuf[64];
__device__ __align__(16) float g_gate_raw[348160];
__device__ __align__(16) float g_gi[348160];

// ---------------- constants ----------------
__constant__ int   c_HW[4]      = {16384, 4096, 1024, 256};
__constant__ int   c_W[4]       = {128, 64, 32, 16};
__constant__ int   c_lw[4]      = {7, 6, 5, 4};
__constant__ int   c_pixBase[4] = {0, 262144, 327680, 344064};
__constant__ int   c_gateOut[4] = {89128960, 89391104, 89456640, 89473024};
__constant__ float c_step[4]    = {2.f/127.f, 2.f/63.f, 2.f/31.f, 2.f/15.f};

// ---------------- packed f32x2 helpers ----------------
__device__ __forceinline__ ull pk2(float lo, float hi) {
    ull r;
    asm("mov.b64 %0,{%1,%2};" : "=l"(r) : "f"(lo), "f"(hi));
    return r;
}
__device__ __forceinline__ void fma2(ull& d, ull a, ull b) {
    asm("fma.rn.f32x2 %0,%1,%2,%0;" : "+l"(d) : "l"(a), "l"(b));
}
__device__ __forceinline__ float2 unpk2(ull v) {
    float2 f;
    asm("mov.b64 {%0,%1},%2;" : "=f"(f.x), "=f"(f.y) : "l"(v));
    return f;
}

// ================= prep: blocks 0..39 = KV tiles (8 rows); 40..55 = mod MLPs =================
#define KV_ROWS 8
__global__ __launch_bounds__(256) void prep_kernel(
    const float* __restrict__ wt, const float* __restrict__ Wk, const float* __restrict__ Wv,
    const float* __restrict__ sent,
    const float* __restrict__ gw1, const float* __restrict__ gb1,
    const float* __restrict__ gw2, const float* __restrict__ gb2,
    const float* __restrict__ bw1, const float* __restrict__ bb1,
    const float* __restrict__ bw2, const float* __restrict__ bb2,
    const float* __restrict__ dw1, const float* __restrict__ db1,
    const float* __restrict__ dw2, const float* __restrict__ db2)
{
    __shared__ __align__(16) float swt[KV_ROWS*DT];
    __shared__ __align__(16) float ss[DT];
    __shared__ float sh[CNUM];
    int t = threadIdx.x;
    int bid = blockIdx.x;

    if (bid < 40) {
        if (bid == 0 && t < 64) g_maxbuf[t] = 0;
        int r0 = bid * KV_ROWS;
        for (int i = t; i < KV_ROWS*DT; i += 256) swt[i] = wt[(size_t)r0*DT + i];
        __syncthreads();
        float aK[KV_ROWS], aV[KV_ROWS];
#pragma unroll
        for (int r = 0; r < KV_ROWS; ++r) { aK[r] = 0.f; aV[r] = 0.f; }
        int c = t;
        for (int d = 0; d < DT; d += 4) {
            float k0 = Wk[(d+0)*CNUM + c], k1 = Wk[(d+1)*CNUM + c];
            float k2 = Wk[(d+2)*CNUM + c], k3 = Wk[(d+3)*CNUM + c];
            float v0 = Wv[(d+0)*CNUM + c], v1 = Wv[(d+1)*CNUM + c];
            float v2 = Wv[(d+2)*CNUM + c], v3 = Wv[(d+3)*CNUM + c];
#pragma unroll
            for (int r = 0; r < KV_ROWS; ++r) {
                float4 w = *reinterpret_cast<const float4*>(&swt[r*DT + d]);
                aK[r] = fmaf(w.x, k0, aK[r]); aK[r] = fmaf(w.y, k1, aK[r]);
                aK[r] = fmaf(w.z, k2, aK[r]); aK[r] = fmaf(w.w, k3, aK[r]);
                aV[r] = fmaf(w.x, v0, aV[r]); aV[r] = fmaf(w.y, v1, aV[r]);
                aV[r] = fmaf(w.z, v2, aV[r]); aV[r] = fmaf(w.w, v3, aV[r]);
            }
        }
#pragma unroll
        for (int r = 0; r < KV_ROWS; ++r) {
            g_K[(r0 + r)*CNUM + c] = aK[r];
            g_V[(r0 + r)*CNUM + c] = aV[r];
        }
    } else {
        int b = bid - 40;
        for (int i = t; i < DT; i += 256) ss[i] = sent[b*DT + i];
        __syncthreads();
        {
            float a0=0,a1=0,a2=0,a3=0;
            for (int d = 0; d < DT; d += 4) {
                float4 s = *reinterpret_cast<const float4*>(&ss[d]);
                a0 = fmaf(s.x, gw1[(d+0)*CNUM + t], a0);
                a1 = fmaf(s.y, gw1[(d+1)*CNUM + t], a1);
                a2 = fmaf(s.z, gw1[(d+2)*CNUM + t], a2);
                a3 = fmaf(s.w, gw1[(d+3)*CNUM + t], a3);
            }
            sh[t] = fmaxf((a0+a1)+(a2+a3) + gb1[t], 0.f);
        }
        __syncthreads();
        {
            float a0=0,a1=0,a2=0,a3=0;
            for (int j = 0; j < CNUM; j += 4) {
                float4 s = *reinterpret_cast<const float4*>(&sh[j]);
                a0 = fmaf(s.x, gw2[(j+0)*CNUM + t], a0);
                a1 = fmaf(s.y, gw2[(j+1)*CNUM + t], a1);
                a2 = fmaf(s.z, gw2[(j+2)*CNUM + t], a2);
                a3 = fmaf(s.w, gw2[(j+3)*CNUM + t], a3);
            }
            g_scale[b*CNUM + t] = 1.f + (a0+a1)+(a2+a3) + gb2[t];
        }
        __syncthreads();
        {
            float a0=0,a1=0,a2=0,a3=0;
            for (int d = 0; d < DT; d += 4) {
                float4 s = *reinterpret_cast<const float4*>(&ss[d]);
                a0 = fmaf(s.x, bw1[(d+0)*CNUM + t], a0);
                a1 = fmaf(s.y, bw1[(d+1)*CNUM + t], a1);
                a2 = fmaf(s.z, bw1[(d+2)*CNUM + t], a2);
                a3 = fmaf(s.w, bw1[(d+3)*CNUM + t], a3);
            }
            sh[t] = fmaxf((a0+a1)+(a2+a3) + bb1[t], 0.f);
        }
        __syncthreads();
        {
            float a0=0,a1=0,a2=0,a3=0;
            for (int j = 0; j < CNUM; j += 4) {
                float4 s = *reinterpret_cast<const float4*>(&sh[j]);
                a0 = fmaf(s.x, bw2[(j+0)*CNUM + t], a0);
                a1 = fmaf(s.y, bw2[(j+1)*CNUM + t], a1);
                a2 = fmaf(s.z, bw2[(j+2)*CNUM + t], a2);
                a3 = fmaf(s.w, bw2[(j+3)*CNUM + t], a3);
            }
            g_beta[b*CNUM + t] = (a0+a1)+(a2+a3) + bb2[t];
        }
        __syncthreads();
        if (t < 64) {
            float a0=0,a1=0,a2=0,a3=0;
            for (int d = 0; d < DT; d += 4) {
                float4 s = *reinterpret_cast<const float4*>(&ss[d]);
                a0 = fmaf(s.x, dw1[(d+0)*64 + t], a0);
                a1 = fmaf(s.y, dw1[(d+1)*64 + t], a1);
                a2 = fmaf(s.z, dw1[(d+2)*64 + t], a2);
                a3 = fmaf(s.w, dw1[(d+3)*64 + t], a3);
            }
            sh[t] = fmaxf((a0+a1)+(a2+a3) + db1[t], 0.f);
        }
        __syncthreads();
        if (t == 0) {
            float v0 = db2[0], v1 = db2[1];
            for (int j = 0; j < 64; ++j) {
                v0 = fmaf(sh[j], dw2[j*2 + 0], v0);
                v1 = fmaf(sh[j], dw2[j*2 + 1], v1);
            }
            float nrm = fmaxf(sqrtf(v0*v0 + v1*v1), 1e-12f);
            g_vec2[b*2 + 0] = v0 / nrm;
            g_vec2[b*2 + 1] = v1 / nrm;
        }
    }
}

// ================= blocks 0..39: M = (K@Wq)/16; 40..55: G = V@V^T =================
__global__ __launch_bounds__(256) void mv_kernel(const float* __restrict__ Wq) {
    __shared__ __align__(16) float sK[KV_ROWS*CNUM];
    __shared__ __align__(16) float sV[LNUM*CNUM];
    int t = threadIdx.x;
    int bid = blockIdx.x;
    if (bid < 40) {
        int r0 = bid * KV_ROWS;
        for (int i = t; i < KV_ROWS*CNUM; i += 256) sK[i] = g_K[r0*CNUM + i];
        __syncthreads();
        float acc[KV_ROWS];
#pragma unroll
        for (int r = 0; r < KV_ROWS; ++r) acc[r] = 0.f;
        int c = t;
        for (int o = 0; o < CNUM; o += 4) {
            float q0 = Wq[(o+0)*CNUM + c], q1 = Wq[(o+1)*CNUM + c];
            float q2 = Wq[(o+2)*CNUM + c], q3 = Wq[(o+3)*CNUM + c];
#pragma unroll
            for (int r = 0; r < KV_ROWS; ++r) {
                float4 k = *reinterpret_cast<const float4*>(&sK[r*CNUM + o]);
                acc[r] = fmaf(k.x, q0, acc[r]); acc[r] = fmaf(k.y, q1, acc[r]);
                acc[r] = fmaf(k.z, q2, acc[r]); acc[r] = fmaf(k.w, q3, acc[r]);
            }
        }
#pragma unroll
        for (int r = 0; r < KV_ROWS; ++r)
            g_M[(r0 + r)*CNUM + c] = acc[r] * 0.0625f;
    } else {
        int b = bid - 40;
        for (int i = t; i < LNUM*CNUM; i += 256) sV[i] = g_V[b*LNUM*CNUM + i];
        __syncthreads();
        for (int e = t; e < LNUM*LNUM; e += 256) {
            int l  = e / LNUM;
            int l2 = e % LNUM;
            float a0=0,a1=0,a2=0,a3=0;
            for (int c = 0; c < CNUM; c += 4) {
                float4 x = *reinterpret_cast<const float4*>(&sV[l*CNUM + c]);
                float4 y = *reinterpret_cast<const float4*>(&sV[l2*CNUM + c]);
                a0 = fmaf(x.x, y.x, a0); a1 = fmaf(x.y, y.y, a1);
                a2 = fmaf(x.z, y.z, a2); a3 = fmaf(x.w, y.w, a3);
            }
            g_G[b*LNUM*LNUM + e] = (a0+a1)+(a2+a3);
        }
    }
}

// ================= Phase A level-0: 4 px/thread (2 packed pairs), 256 blocks =================
__global__ __launch_bounds__(256, 2) void phaseA_L0(const float* __restrict__ f0,
                                                    const int* __restrict__ mask) {
    __shared__ __align__(16) ull sM2[LNUM*CNUM];
    __shared__ __align__(16) ull sG2[LNUM*LNUM];
    __shared__ int smask[LNUM];

    int b    = blockIdx.x >> 4;
    int tile = blockIdx.x & 15;
    int t = threadIdx.x;
    int bbase = b * LNUM * CNUM;
    for (int i = t; i < LNUM*CNUM; i += 256) { float m = g_M[bbase + i]; sM2[i] = pk2(m, m); }
    for (int i = t; i < LNUM*LNUM; i += 256) { float g = g_G[b*LNUM*LNUM + i]; sG2[i] = pk2(g, g); }
    if (t < LNUM) smask[t] = mask[b*LNUM + t];
    __syncthreads();

    const int HW = 16384;
    int n0 = tile * 1024 + t * 4;
    const float* p = f0 + (size_t)b * CNUM * HW + n0;

    ull acc0[LNUM], acc1[LNUM];
#pragma unroll
    for (int l = 0; l < LNUM; ++l) { acc0[l] = 0ull; acc1[l] = 0ull; }

#pragma unroll 4
    for (int c = 0; c < CNUM; c += 2) {
        ulonglong2 A = __ldcs(reinterpret_cast<const ulonglong2*>(p));        // ch c: px0-3
        ulonglong2 B = __ldcs(reinterpret_cast<const ulonglong2*>(p + HW));   // ch c+1
        p += 2 * HW;
#pragma unroll
        for (int l = 0; l < LNUM; ++l) {
            ulonglong2 m = *reinterpret_cast<const ulonglong2*>(&sM2[l*CNUM + c]);
            fma2(acc0[l], A.x, m.x);
            fma2(acc1[l], A.y, m.x);
            fma2(acc0[l], B.x, m.y);
            fma2(acc1[l], B.y, m.y);
        }
    }

    // softmax (both pairs), normalization folded into gate
    float2 mx0 = make_float2(-1e30f, -1e30f), mx1 = mx0;
#pragma unroll
    for (int l = 0; l < LNUM; ++l) {
        if (smask[l]) {
            float2 u0 = unpk2(acc0[l]), u1 = unpk2(acc1[l]);
            mx0.x = fmaxf(mx0.x, u0.x); mx0.y = fmaxf(mx0.y, u0.y);
            mx1.x = fmaxf(mx1.x, u1.x); mx1.y = fmaxf(mx1.y, u1.y);
        }
    }
    float2 sm0 = make_float2(0.f, 0.f), sm1 = sm0;
#pragma unroll
    for (int l = 0; l < LNUM; ++l) {
        int mk = smask[l];
        float2 u0 = unpk2(acc0[l]), u1 = unpk2(acc1[l]);
        float e0 = mk ? __expf(u0.x - mx0.x) : 0.f;
        float e1 = mk ? __expf(u0.y - mx0.y) : 0.f;
        float e2 = mk ? __expf(u1.x - mx1.x) : 0.f;
        float e3 = mk ? __expf(u1.y - mx1.y) : 0.f;
        sm0.x += e0; sm0.y += e1; sm1.x += e2; sm1.y += e3;
        acc0[l] = pk2(e0, e1);
        acc1[l] = pk2(e2, e3);
    }

    ull gs0 = 0ull, gs1 = 0ull;
#pragma unroll
    for (int l = 0; l < LNUM; ++l) {
        ull t0 = 0ull, t1 = 0ull;
#pragma unroll
        for (int l2 = 0; l2 < LNUM; l2 += 2) {
            ulonglong2 gg = *reinterpret_cast<const ulonglong2*>(&sG2[l*LNUM + l2]);
            fma2(t0, acc0[l2],   gg.x);
            fma2(t0, acc0[l2+1], gg.y);
            fma2(t1, acc1[l2],   gg.x);
            fma2(t1, acc1[l2+1], gg.y);
        }
        fma2(gs0, acc0[l], t0);
        fma2(gs1, acc1[l], t1);
    }
    float2 g0 = unpk2(gs0), g1 = unpk2(gs1);
    float4 gt;
    gt.x = sqrtf(fmaxf(g0.x, 0.f)) * __fdividef(1.f, sm0.x);
    gt.y = sqrtf(fmaxf(g0.y, 0.f)) * __fdividef(1.f, sm0.y);
    gt.z = sqrtf(fmaxf(g1.x, 0.f)) * __fdividef(1.f, sm1.x);
    gt.w = sqrtf(fmaxf(g1.y, 0.f)) * __fdividef(1.f, sm1.y);
    *reinterpret_cast<float4*>(&g_gate_raw[b*HW + n0]) = gt;
    float m01 = fmaxf(gt.x, gt.y), m23 = fmaxf(gt.z, gt.w);
    atomicMax(&g_maxbuf[b], __float_as_int(fmaxf(m01, m23)));
}

// ---------------- phaseA core (NP=1, levels 1-3) ----------------
template<int HW>
__device__ __forceinline__ void phaseA_core(const float* __restrict__ F, int b, int n0,
                                            const ull* __restrict__ sM2,
                                            const ull* __restrict__ sG2,
                                            const int* __restrict__ smask,
                                            int pbase, int maxSlot) {
    const float* p = F + (size_t)b * CNUM * HW + n0;

    ull acc[LNUM];
#pragma unroll
    for (int l = 0; l < LNUM; ++l) acc[l] = 0ull;

#pragma unroll 8
    for (int c = 0; c < CNUM; c += 2) {
        ull fa = __ldcs(reinterpret_cast<const ull*>(p));
        ull fb = __ldcs(reinterpret_cast<const ull*>(p + HW));
        p += 2 * HW;
#pragma unroll
        for (int l = 0; l < LNUM; ++l) {
            ulonglong2 m = *reinterpret_cast<const ulonglong2*>(&sM2[l*CNUM + c]);
            fma2(acc[l], fa, m.x);
            fma2(acc[l], fb, m.y);
        }
    }

    float2 mx = make_float2(-1e30f, -1e30f);
#pragma unroll
    for (int l = 0; l < LNUM; ++l) {
        if (smask[l]) {
            float2 u = unpk2(acc[l]);
            mx.x = fmaxf(mx.x, u.x);
            mx.y = fmaxf(mx.y, u.y);
        }
    }
    float2 sm = make_float2(0.f, 0.f);
#pragma unroll
    for (int l = 0; l < LNUM; ++l) {
        int mk = smask[l];
        float2 u = unpk2(acc[l]);
        float e0 = mk ? __expf(u.x - mx.x) : 0.f;
        float e1 = mk ? __expf(u.y - mx.y) : 0.f;
        sm.x += e0; sm.y += e1;
        acc[l] = pk2(e0, e1);
    }

    ull gs = 0ull;
#pragma unroll
    for (int l = 0; l < LNUM; ++l) {
        ull tt = 0ull;
#pragma unroll
        for (int l2 = 0; l2 < LNUM; l2 += 2) {
            ulonglong2 gg = *reinterpret_cast<const ulonglong2*>(&sG2[l*LNUM + l2]);
            fma2(tt, acc[l2],   gg.x);
            fma2(tt, acc[l2+1], gg.y);
        }
        fma2(gs, acc[l], tt);
    }
    float2 g0 = unpk2(gs);
    float2 gt;
    gt.x = sqrtf(fmaxf(g0.x, 0.f)) * __fdividef(1.f, sm.x);
    gt.y = sqrtf(fmaxf(g0.y, 0.f)) * __fdividef(1.f, sm.y);
    *reinterpret_cast<float2*>(&g_gate_raw[pbase + n0]) = gt;
    atomicMax(&g_maxbuf[maxSlot], __float_as_int(fmaxf(gt.x, gt.y)));
}

// ================= Phase A rest (levels 1-3): 176 blocks =================
__global__ __launch_bounds__(256, 3) void phaseA_rest(const float* __restrict__ f1,
                                                      const float* __restrict__ f2,
                                                      const float* __restrict__ f3,
                                                      const int* __restrict__ mask) {
    __shared__ __align__(16) ull sM2[LNUM*CNUM];
    __shared__ __align__(16) ull sG2[LNUM*LNUM];
    __shared__ int smask[LNUM];

    int bid = blockIdx.x;
    int level, b, tile;
    if (bid < 128)      { level = 1; b = bid >> 3; tile = bid & 7; }
    else if (bid < 160) { int r = bid - 128; level = 2; b = r >> 1; tile = r & 1; }
    else                { level = 3; b = bid - 160; tile = 0; }

    int t = threadIdx.x;
    int bbase = b * LNUM * CNUM;
    for (int i = t; i < LNUM*CNUM; i += 256) { float m = g_M[bbase + i]; sM2[i] = pk2(m, m); }
    for (int i = t; i < LNUM*LNUM; i += 256) { float g = g_G[b*LNUM*LNUM + i]; sG2[i] = pk2(g, g); }
    if (t < LNUM) smask[t] = mask[b*LNUM + t];
    __syncthreads();

    int n0 = tile * 512 + 2 * t;
    if (level == 1)
        phaseA_core< 4096>(f1, b, n0, sM2, sG2, smask, 262144 + b*4096, 16 + b);
    else if (level == 2)
        phaseA_core< 1024>(f2, b, n0, sM2, sG2, smask, 327680 + b*1024, 32 + b);
    else if (t < 128)
        phaseA_core<  256>(f3, b, 2*t, sM2, sG2, smask, 344064 + b*256, 48 + b);
}

// ---------------- block decode: 688 blocks (phaseA2) ----------------
__device__ __forceinline__ void decode_block(int bid, int& level, int& b, int& tile) {
    if (bid < 512)      { level = 0; b = bid >> 5; tile = bid & 31; }
    else if (bid < 640) { int r = bid - 512; level = 1; b = r >> 3; tile = r & 7; }
    else if (bid < 672) { int r = bid - 640; level = 2; b = r >> 1; tile = r & 1; }
    else                { level = 3; b = bid - 672; tile = 0; }
}

// ================= Phase A2 =================
__global__ __launch_bounds__(256) void phaseA2(float* __restrict__ out) {
    int level, b, tile;
    decode_block(blockIdx.x, level, b, tile);
    int t = threadIdx.x;
    const int HW = c_HW[level];
    const int W  = c_W[level];
    const int lw = c_lw[level];
    float step = c_step[level];
    float v0 = g_vec2[2*b], v1 = g_vec2[2*b + 1];
    float mxv = __int_as_float(g_maxbuf[level*16 + b]) + 1e-6f;
    int pbase = c_pixBase[level] + b*HW;
    int obase = c_gateOut[level] + b*HW;
#pragma unroll
    for (int p = 0; p < 2; ++p) {
        int n = tile * 512 + t + p * 256;
        if (n >= HW) break;
        int w = n & (W - 1);
        int h = n >> lw;
        float x = fmaf((float)w, step, -1.f);
        float y = fmaf((float)h, step, -1.f);
        float pr = v0 * x + v1 * y;
        float di = __fdividef(1.f, 1.f + __expf(-pr));
        float gi = __fdividef(g_gate_raw[pbase + n], mxv) * di;
        g_gi[pbase + n] = gi;
        out[obase + n] = gi;
    }
}

// ================= Phase B (flat): 4 consecutive float4/thread =================
template<int HW, int LG>
__device__ __forceinline__ void phaseB_core(const float* __restrict__ F,
                                            float* __restrict__ out,
                                            int g, int pixBase) {
    int n4   = g & (HW/4 - 1);
    int rest = g >> LG;
    int c = rest & 255;
    int b = rest >> 8;
    float sc = g_scale[b*CNUM + c];
    float be = g_beta[b*CNUM + c];
    const float4* fp = reinterpret_cast<const float4*>(F) + g;
    const float4* gp = reinterpret_cast<const float4*>(&g_gi[pixBase + b*HW]) + n4;
    float4*       op = reinterpret_cast<float4*>(out) + g;
#pragma unroll
    for (int j = 0; j < 4; ++j) {
        float4 f  = __ldcs(&fp[j]);
        float4 gi = gp[j];
        float4 o;
        o.x = fmaf(gi.x * f.x, sc, be);
        o.y = fmaf(gi.y * f.y, sc, be);
        o.z = fmaf(gi.z * f.z, sc, be);
        o.w = fmaf(gi.w * f.w, sc, be);
        __stcs(&op[j], o);
    }
}

__global__ __launch_bounds__(256) void phaseB(const float* __restrict__ f0,
                                              const float* __restrict__ f1,
                                              const float* __restrict__ f2,
                                              const float* __restrict__ f3,
                                              float* __restrict__ out) {
    int bid = blockIdx.x;
    int t = threadIdx.x;
    if (bid < 16384) {
        int g = bid * 1024 + t * 4;
        phaseB_core<16384, 12>(f0, out, g, 0);
    } else if (bid < 20480) {
        int g = (bid - 16384) * 1024 + t * 4;
        phaseB_core<4096, 10>(f1, out + 67108864, g, 262144);
    } else if (bid < 21504) {
        int g = (bid - 20480) * 1024 + t * 4;
        phaseB_core<1024, 8>(f2, out + 83886080, g, 327680);
    } else {
        int g = (bid - 21504) * 1024 + t * 4;
        phaseB_core<256, 6>(f3, out + 88080384, g, 344064);
    }
}

// ================= launch =================
extern "C" void kernel_launch(void* const* d_in, const int* in_sizes, int n_in,
                              void* d_out, int out_size) {
    const float* f0   = (const float*)d_in[0];
    const float* f1   = (const float*)d_in[1];
    const float* f2   = (const float*)d_in[2];
    const float* f3   = (const float*)d_in[3];
    const float* wt   = (const float*)d_in[4];
    const float* sent = (const float*)d_in[5];
    const int*   mask = (const int*)  d_in[6];
    const float* Wq   = (const float*)d_in[7];
    const float* Wk   = (const float*)d_in[8];
    const float* Wv   = (const float*)d_in[9];
    const float* gw1  = (const float*)d_in[10];
    const float* gb1  = (const float*)d_in[11];
    const float* gw2  = (const float*)d_in[12];
    const float* gb2  = (const float*)d_in[13];
    const float* bw1  = (const float*)d_in[14];
    const float* bb1  = (const float*)d_in[15];
    const float* bw2  = (const float*)d_in[16];
    const float* bb2  = (const float*)d_in[17];
    const float* dw1  = (const float*)d_in[18];
    const float* db1  = (const float*)d_in[19];
    const float* dw2  = (const float*)d_in[20];
    const float* db2  = (const float*)d_in[21];
    float* out = (float*)d_out;

    prep_kernel<<<56, 256>>>(wt, Wk, Wv, sent, gw1, gb1, gw2, gb2,
                             bw1, bb1, bw2, bb2, dw1, db1, dw2, db2);
    mv_kernel<<<56, 256>>>(Wq);
    phaseA_rest<<<176, 256>>>(f1, f2, f3, mask);
    phaseA_L0<<<256, 256>>>(f0, mask);
    phaseA2<<<688, 256>>>(out);
    phaseB<<<21760, 256>>>(f0, f1, f2, f3, out);
}

// round 12
// speedup vs baseline: 1.2220x; 1.1057x over previous
#include <cuda_runtime.h>
#include <math.h>

#define BNUM 16
#define LNUM 20
#define CNUM 256
#define DT   768

typedef unsigned long long ull;

// ---------------- scratch ----------------
__device__ float g_K[BNUM*LNUM*CNUM];
__device__ float g_V[BNUM*LNUM*CNUM];
__device__ float g_M[BNUM*LNUM*CNUM];
__device__ float g_G[BNUM*LNUM*LNUM];
__device__ float g_scale[BNUM*CNUM];
__device__ float g_beta[BNUM*CNUM];
__device__ float g_vec2[BNUM*2];
__device__ int   g_maxbuf[64];
__device__ __align__(16) float g_gate_raw[348160];
__device__ __align__(16) float g_gi[348160];

// ---------------- constants ----------------
__constant__ int   c_HW[4]      = {16384, 4096, 1024, 256};
__constant__ int   c_W[4]       = {128, 64, 32, 16};
__constant__ int   c_lw[4]      = {7, 6, 5, 4};
__constant__ int   c_pixBase[4] = {0, 262144, 327680, 344064};
__constant__ int   c_gateOut[4] = {89128960, 89391104, 89456640, 89473024};
__constant__ float c_step[4]    = {2.f/127.f, 2.f/63.f, 2.f/31.f, 2.f/15.f};

// ---------------- packed f32x2 helpers ----------------
__device__ __forceinline__ ull pk2(float lo, float hi) {
    ull r;
    asm("mov.b64 %0,{%1,%2};" : "=l"(r) : "f"(lo), "f"(hi));
    return r;
}
__device__ __forceinline__ void fma2(ull& d, ull a, ull b) {
    asm("fma.rn.f32x2 %0,%1,%2,%0;" : "+l"(d) : "l"(a), "l"(b));
}
__device__ __forceinline__ float2 unpk2(ull v) {
    float2 f;
    asm("mov.b64 {%0,%1},%2;" : "=f"(f.x), "=f"(f.y) : "l"(v));
    return f;
}

// ================= prep: blocks 0..39 = KV tiles (8 rows); 40..55 = mod MLPs =================
#define KV_ROWS 8
__global__ __launch_bounds__(256) void prep_kernel(
    const float* __restrict__ wt, const float* __restrict__ Wk, const float* __restrict__ Wv,
    const float* __restrict__ sent,
    const float* __restrict__ gw1, const float* __restrict__ gb1,
    const float* __restrict__ gw2, const float* __restrict__ gb2,
    const float* __restrict__ bw1, const float* __restrict__ bb1,
    const float* __restrict__ bw2, const float* __restrict__ bb2,
    const float* __restrict__ dw1, const float* __restrict__ db1,
    const float* __restrict__ dw2, const float* __restrict__ db2)
{
    __shared__ __align__(16) float swt[KV_ROWS*DT];
    __shared__ __align__(16) float ss[DT];
    __shared__ float sh[CNUM];
    int t = threadIdx.x;
    int bid = blockIdx.x;

    if (bid < 40) {
        if (bid == 0 && t < 64) g_maxbuf[t] = 0;
        int r0 = bid * KV_ROWS;
        for (int i = t; i < KV_ROWS*DT; i += 256) swt[i] = wt[(size_t)r0*DT + i];
        __syncthreads();
        float aK[KV_ROWS], aV[KV_ROWS];
#pragma unroll
        for (int r = 0; r < KV_ROWS; ++r) { aK[r] = 0.f; aV[r] = 0.f; }
        int c = t;
        for (int d = 0; d < DT; d += 4) {
            float k0 = Wk[(d+0)*CNUM + c], k1 = Wk[(d+1)*CNUM + c];
            float k2 = Wk[(d+2)*CNUM + c], k3 = Wk[(d+3)*CNUM + c];
            float v0 = Wv[(d+0)*CNUM + c], v1 = Wv[(d+1)*CNUM + c];
            float v2 = Wv[(d+2)*CNUM + c], v3 = Wv[(d+3)*CNUM + c];
#pragma unroll
            for (int r = 0; r < KV_ROWS; ++r) {
                float4 w = *reinterpret_cast<const float4*>(&swt[r*DT + d]);
                aK[r] = fmaf(w.x, k0, aK[r]); aK[r] = fmaf(w.y, k1, aK[r]);
                aK[r] = fmaf(w.z, k2, aK[r]); aK[r] = fmaf(w.w, k3, aK[r]);
                aV[r] = fmaf(w.x, v0, aV[r]); aV[r] = fmaf(w.y, v1, aV[r]);
                aV[r] = fmaf(w.z, v2, aV[r]); aV[r] = fmaf(w.w, v3, aV[r]);
            }
        }
#pragma unroll
        for (int r = 0; r < KV_ROWS; ++r) {
            g_K[(r0 + r)*CNUM + c] = aK[r];
            g_V[(r0 + r)*CNUM + c] = aV[r];
        }
    } else {
        int b = bid - 40;
        for (int i = t; i < DT; i += 256) ss[i] = sent[b*DT + i];
        __syncthreads();
        {
            float a0=0,a1=0,a2=0,a3=0;
            for (int d = 0; d < DT; d += 4) {
                float4 s = *reinterpret_cast<const float4*>(&ss[d]);
                a0 = fmaf(s.x, gw1[(d+0)*CNUM + t], a0);
                a1 = fmaf(s.y, gw1[(d+1)*CNUM + t], a1);
                a2 = fmaf(s.z, gw1[(d+2)*CNUM + t], a2);
                a3 = fmaf(s.w, gw1[(d+3)*CNUM + t], a3);
            }
            sh[t] = fmaxf((a0+a1)+(a2+a3) + gb1[t], 0.f);
        }
        __syncthreads();
        {
            float a0=0,a1=0,a2=0,a3=0;
            for (int j = 0; j < CNUM; j += 4) {
                float4 s = *reinterpret_cast<const float4*>(&sh[j]);
                a0 = fmaf(s.x, gw2[(j+0)*CNUM + t], a0);
                a1 = fmaf(s.y, gw2[(j+1)*CNUM + t], a1);
                a2 = fmaf(s.z, gw2[(j+2)*CNUM + t], a2);
                a3 = fmaf(s.w, gw2[(j+3)*CNUM + t], a3);
            }
            g_scale[b*CNUM + t] = 1.f + (a0+a1)+(a2+a3) + gb2[t];
        }
        __syncthreads();
        {
            float a0=0,a1=0,a2=0,a3=0;
            for (int d = 0; d < DT; d += 4) {
                float4 s = *reinterpret_cast<const float4*>(&ss[d]);
                a0 = fmaf(s.x, bw1[(d+0)*CNUM + t], a0);
                a1 = fmaf(s.y, bw1[(d+1)*CNUM + t], a1);
                a2 = fmaf(s.z, bw1[(d+2)*CNUM + t], a2);
                a3 = fmaf(s.w, bw1[(d+3)*CNUM + t], a3);
            }
            sh[t] = fmaxf((a0+a1)+(a2+a3) + bb1[t], 0.f);
        }
        __syncthreads();
        {
            float a0=0,a1=0,a2=0,a3=0;
            for (int j = 0; j < CNUM; j += 4) {
                float4 s = *reinterpret_cast<const float4*>(&sh[j]);
                a0 = fmaf(s.x, bw2[(j+0)*CNUM + t], a0);
                a1 = fmaf(s.y, bw2[(j+1)*CNUM + t], a1);
                a2 = fmaf(s.z, bw2[(j+2)*CNUM + t], a2);
                a3 = fmaf(s.w, bw2[(j+3)*CNUM + t], a3);
            }
            g_beta[b*CNUM + t] = (a0+a1)+(a2+a3) + bb2[t];
        }
        __syncthreads();
        if (t < 64) {
            float a0=0,a1=0,a2=0,a3=0;
            for (int d = 0; d < DT; d += 4) {
                float4 s = *reinterpret_cast<const float4*>(&ss[d]);
                a0 = fmaf(s.x, dw1[(d+0)*64 + t], a0);
                a1 = fmaf(s.y, dw1[(d+1)*64 + t], a1);
                a2 = fmaf(s.z, dw1[(d+2)*64 + t], a2);
                a3 = fmaf(s.w, dw1[(d+3)*64 + t], a3);
            }
            sh[t] = fmaxf((a0+a1)+(a2+a3) + db1[t], 0.f);
        }
        __syncthreads();
        if (t == 0) {
            float v0 = db2[0], v1 = db2[1];
            for (int j = 0; j < 64; ++j) {
                v0 = fmaf(sh[j], dw2[j*2 + 0], v0);
                v1 = fmaf(sh[j], dw2[j*2 + 1], v1);
            }
            float nrm = fmaxf(sqrtf(v0*v0 + v1*v1), 1e-12f);
            g_vec2[b*2 + 0] = v0 / nrm;
            g_vec2[b*2 + 1] = v1 / nrm;
        }
    }
}

// ================= blocks 0..39: M = (K@Wq)/16; 40..55: G = V@V^T =================
__global__ __launch_bounds__(256) void mv_kernel(const float* __restrict__ Wq) {
    __shared__ __align__(16) float sK[KV_ROWS*CNUM];
    __shared__ __align__(16) float sV[LNUM*CNUM];
    int t = threadIdx.x;
    int bid = blockIdx.x;
    if (bid < 40) {
        int r0 = bid * KV_ROWS;
        for (int i = t; i < KV_ROWS*CNUM; i += 256) sK[i] = g_K[r0*CNUM + i];
        __syncthreads();
        float acc[KV_ROWS];
#pragma unroll
        for (int r = 0; r < KV_ROWS; ++r) acc[r] = 0.f;
        int c = t;
        for (int o = 0; o < CNUM; o += 4) {
            float q0 = Wq[(o+0)*CNUM + c], q1 = Wq[(o+1)*CNUM + c];
            float q2 = Wq[(o+2)*CNUM + c], q3 = Wq[(o+3)*CNUM + c];
#pragma unroll
            for (int r = 0; r < KV_ROWS; ++r) {
                float4 k = *reinterpret_cast<const float4*>(&sK[r*CNUM + o]);
                acc[r] = fmaf(k.x, q0, acc[r]); acc[r] = fmaf(k.y, q1, acc[r]);
                acc[r] = fmaf(k.z, q2, acc[r]); acc[r] = fmaf(k.w, q3, acc[r]);
            }
        }
#pragma unroll
        for (int r = 0; r < KV_ROWS; ++r)
            g_M[(r0 + r)*CNUM + c] = acc[r] * 0.0625f;
    } else {
        int b = bid - 40;
        for (int i = t; i < LNUM*CNUM; i += 256) sV[i] = g_V[b*LNUM*CNUM + i];
        __syncthreads();
        for (int e = t; e < LNUM*LNUM; e += 256) {
            int l  = e / LNUM;
            int l2 = e % LNUM;
            float a0=0,a1=0,a2=0,a3=0;
            for (int c = 0; c < CNUM; c += 4) {
                float4 x = *reinterpret_cast<const float4*>(&sV[l*CNUM + c]);
                float4 y = *reinterpret_cast<const float4*>(&sV[l2*CNUM + c]);
                a0 = fmaf(x.x, y.x, a0); a1 = fmaf(x.y, y.y, a1);
                a2 = fmaf(x.z, y.z, a2); a3 = fmaf(x.w, y.w, a3);
            }
            g_G[b*LNUM*LNUM + e] = (a0+a1)+(a2+a3);
        }
    }
}

// ---------------- block decode: 688 blocks (phaseA / phaseA2) ----------------
__device__ __forceinline__ void decode_block(int bid, int& level, int& b, int& tile) {
    if (bid < 512)      { level = 0; b = bid >> 5; tile = bid & 31; }
    else if (bid < 640) { int r = bid - 512; level = 1; b = r >> 3; tile = r & 7; }
    else if (bid < 672) { int r = bid - 640; level = 2; b = r >> 1; tile = r & 1; }
    else                { level = 3; b = bid - 672; tile = 0; }
}

// ---------------- phaseA core (NP=1) ----------------
template<int HW>
__device__ __forceinline__ void phaseA_core(const float* __restrict__ F, int b, int n0,
                                            const ull* __restrict__ sM2,
                                            const ull* __restrict__ sG2,
                                            const int* __restrict__ smask,
                                            int pbase, int maxSlot) {
    const float* p = F + (size_t)b * CNUM * HW + n0;

    ull acc[LNUM];
#pragma unroll
    for (int l = 0; l < LNUM; ++l) acc[l] = 0ull;

#pragma unroll 8
    for (int c = 0; c < CNUM; c += 2) {
        ull fa = __ldcs(reinterpret_cast<const ull*>(p));
        ull fb = __ldcs(reinterpret_cast<const ull*>(p + HW));
        p += 2 * HW;
#pragma unroll
        for (int l = 0; l < LNUM; ++l) {
            ulonglong2 m = *reinterpret_cast<const ulonglong2*>(&sM2[l*CNUM + c]);
            fma2(acc[l], fa, m.x);
            fma2(acc[l], fb, m.y);
        }
    }

    float2 mx = make_float2(-1e30f, -1e30f);
#pragma unroll
    for (int l = 0; l < LNUM; ++l) {
        if (smask[l]) {
            float2 u = unpk2(acc[l]);
            mx.x = fmaxf(mx.x, u.x);
            mx.y = fmaxf(mx.y, u.y);
        }
    }
    float2 sm = make_float2(0.f, 0.f);
#pragma unroll
    for (int l = 0; l < LNUM; ++l) {
        int mk = smask[l];
        float2 u = unpk2(acc[l]);
        float e0 = mk ? __expf(u.x - mx.x) : 0.f;
        float e1 = mk ? __expf(u.y - mx.y) : 0.f;
        sm.x += e0; sm.y += e1;
        acc[l] = pk2(e0, e1);
    }

    ull gs = 0ull;
#pragma unroll
    for (int l = 0; l < LNUM; ++l) {
        ull tt = 0ull;
#pragma unroll
        for (int l2 = 0; l2 < LNUM; l2 += 2) {
            ulonglong2 gg = *reinterpret_cast<const ulonglong2*>(&sG2[l*LNUM + l2]);
            fma2(tt, acc[l2],   gg.x);
            fma2(tt, acc[l2+1], gg.y);
        }
        fma2(gs, acc[l], tt);
    }
    float2 g0 = unpk2(gs);
    float2 gt;
    gt.x = sqrtf(fmaxf(g0.x, 0.f)) * __fdividef(1.f, sm.x);
    gt.y = sqrtf(fmaxf(g0.y, 0.f)) * __fdividef(1.f, sm.y);
    *reinterpret_cast<float2*>(&g_gate_raw[pbase + n0]) = gt;
    atomicMax(&g_maxbuf[maxSlot], __float_as_int(fmaxf(gt.x, gt.y)));
}

// ================= Phase A (R6 unified, (256,3)) =================
__global__ __launch_bounds__(256, 3) void phaseA(const float* __restrict__ f0,
                                                 const float* __restrict__ f1,
                                                 const float* __restrict__ f2,
                                                 const float* __restrict__ f3,
                                                 const int* __restrict__ mask) {
    __shared__ __align__(16) ull sM2[LNUM*CNUM];
    __shared__ __align__(16) ull sG2[LNUM*LNUM];
    __shared__ int smask[LNUM];

    int level, b, tile;
    decode_block(blockIdx.x, level, b, tile);
    int t = threadIdx.x;
    int bbase = b * LNUM * CNUM;
    for (int i = t; i < LNUM*CNUM; i += 256) { float m = g_M[bbase + i]; sM2[i] = pk2(m, m); }
    for (int i = t; i < LNUM*LNUM; i += 256) { float g = g_G[b*LNUM*LNUM + i]; sG2[i] = pk2(g, g); }
    if (t < LNUM) smask[t] = mask[b*LNUM + t];
    __syncthreads();

    int n0 = tile * 512 + 2 * t;
    if (level == 0)
        phaseA_core<16384>(f0, b, n0, sM2, sG2, smask, b*16384,          b);
    else if (level == 1)
        phaseA_core< 4096>(f1, b, n0, sM2, sG2, smask, 262144 + b*4096, 16 + b);
    else if (level == 2)
        phaseA_core< 1024>(f2, b, n0, sM2, sG2, smask, 327680 + b*1024, 32 + b);
    else if (t < 128)
        phaseA_core<  256>(f3, b, 2*t, sM2, sG2, smask, 344064 + b*256, 48 + b);
}

// ================= Phase A2 =================
__global__ __launch_bounds__(256) void phaseA2(float* __restrict__ out) {
    int level, b, tile;
    decode_block(blockIdx.x, level, b, tile);
    int t = threadIdx.x;
    const int HW = c_HW[level];
    const int W  = c_W[level];
    const int lw = c_lw[level];
    float step = c_step[level];
    float v0 = g_vec2[2*b], v1 = g_vec2[2*b + 1];
    float mxv = __int_as_float(g_maxbuf[level*16 + b]) + 1e-6f;
    int pbase = c_pixBase[level] + b*HW;
    int obase = c_gateOut[level] + b*HW;
#pragma unroll
    for (int p = 0; p < 2; ++p) {
        int n = tile * 512 + t + p * 256;
        if (n >= HW) break;
        int w = n & (W - 1);
        int h = n >> lw;
        float x = fmaf((float)w, step, -1.f);
        float y = fmaf((float)h, step, -1.f);
        float pr = v0 * x + v1 * y;
        float di = __fdividef(1.f, 1.f + __expf(-pr));
        float gi = __fdividef(g_gate_raw[pbase + n], mxv) * di;
        g_gi[pbase + n] = gi;
        out[obase + n] = gi;
    }
}

// ================= Phase B v3: gi-in-registers, 8-channel groups =================
template<int HW>
__device__ __forceinline__ void pB3_core(const float* __restrict__ F,
                                         float* __restrict__ o,
                                         int b, int tile, int cg, int t,
                                         int pixBase) {
    constexpr int TPX = (HW < 1024) ? HW : 1024;
    constexpr int NTH = TPX / 4;
    if (NTH < 256 && t >= NTH) return;
    int n0 = tile * TPX + t * 4;
    float4 gv = *reinterpret_cast<const float4*>(&g_gi[pixBase + b*HW + n0]);
    int c0 = cg * 8;
    size_t base = (size_t)b * CNUM * HW + (size_t)c0 * HW + n0;
    const float4* fp = reinterpret_cast<const float4*>(F + base);
    float4*       op = reinterpret_cast<float4*>(o + base);
    const float* scp = &g_scale[b*CNUM + c0];
    const float* bep = &g_beta [b*CNUM + c0];
    constexpr int S4 = HW / 4;
#pragma unroll
    for (int j = 0; j < 8; ++j) {
        float sc = scp[j];
        float be = bep[j];
        float4 f = __ldcs(fp + j*S4);
        float4 r;
        r.x = fmaf(gv.x * f.x, sc, be);
        r.y = fmaf(gv.y * f.y, sc, be);
        r.z = fmaf(gv.z * f.z, sc, be);
        r.w = fmaf(gv.w * f.w, sc, be);
        __stcs(op + j*S4, r);
    }
}

__global__ __launch_bounds__(256) void phaseB(const float* __restrict__ f0,
                                              const float* __restrict__ f1,
                                              const float* __restrict__ f2,
                                              const float* __restrict__ f3,
                                              float* __restrict__ out) {
    // L0: 16b*16t*32cg = 8192;  L1: 16*4*32 = 2048;  L2: 16*1*32 = 512;  L3: 16*1*32 = 512
    int bid = blockIdx.x;
    int t = threadIdx.x;
    if (bid < 8192) {
        int b = bid >> 9, r = bid & 511;
        pB3_core<16384>(f0, out,            b, r & 15, r >> 4, t, 0);
    } else if (bid < 10240) {
        int r = bid - 8192;
        int b = r >> 7, r2 = r & 127;
        pB3_core< 4096>(f1, out + 67108864, b, r2 & 3, r2 >> 2, t, 262144);
    } else if (bid < 10752) {
        int r = bid - 10240;
        pB3_core< 1024>(f2, out + 83886080, r >> 5, 0, r & 31, t, 327680);
    } else {
        int r = bid - 10752;
        pB3_core<  256>(f3, out + 88080384, r >> 5, 0, r & 31, t, 344064);
    }
}

// ================= launch =================
extern "C" void kernel_launch(void* const* d_in, const int* in_sizes, int n_in,
                              void* d_out, int out_size) {
    const float* f0   = (const float*)d_in[0];
    const float* f1   = (const float*)d_in[1];
    const float* f2   = (const float*)d_in[2];
    const float* f3   = (const float*)d_in[3];
    const float* wt   = (const float*)d_in[4];
    const float* sent = (const float*)d_in[5];
    const int*   mask = (const int*)  d_in[6];
    const float* Wq   = (const float*)d_in[7];
    const float* Wk   = (const float*)d_in[8];
    const float* Wv   = (const float*)d_in[9];
    const float* gw1  = (const float*)d_in[10];
    const float* gb1  = (const float*)d_in[11];
    const float* gw2  = (const float*)d_in[12];
    const float* gb2  = (const float*)d_in[13];
    const float* bw1  = (const float*)d_in[14];
    const float* bb1  = (const float*)d_in[15];
    const float* bw2  = (const float*)d_in[16];
    const float* bb2  = (const float*)d_in[17];
    const float* dw1  = (const float*)d_in[18];
    const float* db1  = (const float*)d_in[19];
    const float* dw2  = (const float*)d_in[20];
    const float* db2  = (const float*)d_in[21];
    float* out = (float*)d_out;

    prep_kernel<<<56, 256>>>(wt, Wk, Wv, sent, gw1, gb1, gw2, gb2,
                             bw1, bb1, bw2, bb2, dw1, db1, dw2, db2);
    mv_kernel<<<56, 256>>>(Wq);
    phaseA<<<688, 256>>>(f0, f1, f2, f3, mask);
    phaseA2<<<688, 256>>>(out);
    phaseB<<<11264, 256>>>(f0, f1, f2, f3, out);
}